// round 13
// baseline (speedup 1.0000x reference)
#include <cuda_runtime.h>
#include <cuda_fp16.h>

#define Nn 50000
#define Ee 800000
#define INF 128
#define HH  128
#define OUTF 64
#define SCAN_BLK 1024
#define SCAN_NB ((Nn + SCAN_BLK - 1) / SCAN_BLK)   // 49

typedef unsigned long long u64;

// ---- packed f32x2 helpers (kept from r8; neutral but harmless) ----
__device__ __forceinline__ u64 pack2(float lo, float hi) {
    u64 r; asm("mov.b64 %0, {%1, %2};" : "=l"(r) : "f"(lo), "f"(hi)); return r;
}
__device__ __forceinline__ void unpack2(u64 v, float& lo, float& hi) {
    asm("mov.b64 {%0, %1}, %2;" : "=f"(lo), "=f"(hi) : "l"(v));
}
__device__ __forceinline__ u64 ffma2(u64 a, u64 b, u64 c) {
    u64 d; asm("fma.rn.f32x2 %0, %1, %2, %3;" : "=l"(d) : "l"(a), "l"(b), "l"(c)); return d;
}

// ---- device scratch (static globals; no allocation) ----
__device__ __align__(16) __half g_h1[Nn * HH];   // (x @ W1) * dinv[row], fp16 for gather
__device__ __align__(16) float  g_h [Nn * HH];   // relu(conv1) output, fp32 (GEMM2 input)
__device__ __align__(16) __half g_m2[Nn * OUTF]; // (h @ Wmu) * dinv[row], fp16 for gather
__device__ int   g_deg [Nn];
__device__ int   g_ptr [Nn + 1];
__device__ int   g_fill[Nn];       // running cursor, initialized to ptr by scan
__device__ int   g_src [Ee];       // CSR-by-dst neighbor lists
__device__ float g_dinv[Nn];
__device__ int   g_is64;           // 1 if edge_index is int64, 0 if int32
__device__ volatile int g_chain[SCAN_NB];  // inclusive prefix through block b
__device__ volatile int g_cflag[SCAN_NB];  // ready flags for chained scan

__device__ __forceinline__ int edge_at(const void* ei, int which, int e, int is64) {
    // which: 0 = src row, 1 = dst row, layout [2, E]
    if (is64) return (int)((const long long*)ei)[(long)which * Ee + e];
    return ((const int*)ei)[(long)which * Ee + e];
}

// ---------------- zero + flag reset + fused dtype detection ----------------
__global__ void k_zero(const void* ei) {
    int i = blockIdx.x * blockDim.x + threadIdx.x;
    if (i < Nn) g_deg[i] = 0;
    if (i < SCAN_NB) g_cflag[i] = 0;
    if (blockIdx.x == 0 && threadIdx.x < 32) {
        int lane = threadIdx.x;
        const long long* p = (const long long*)ei;
        long long v1 = p[lane];            // src row head
        long long v2 = p[Ee + lane];       // dst row head
        bool ok = (v1 >= 0 && v1 < Nn) && (v2 >= 0 && v2 < Nn);
        unsigned all = __all_sync(0xffffffffu, ok);
        if (lane == 0) g_is64 = all ? 1 : 0;
    }
}

__global__ void k_deg(const void* __restrict__ ei) {
    int e = blockIdx.x * blockDim.x + threadIdx.x;
    if (e < Ee) {
        const int is64 = g_is64;
        int d = edge_at(ei, 1, e, is64);
        if (d >= 0 && d < Nn) atomicAdd(&g_deg[d], 1);
    }
}

// ---- single-pass chained scan (49 blocks, all wave-1 co-resident) ----
// Also: fused dinv, g_fill=ptr init, g_ptr[Nn]=Ee.
__global__ void k_scan() {
    __shared__ int warp_sums[32];
    __shared__ int s_prefix;
    int tid = threadIdx.x, lane = tid & 31, wid = tid >> 5;
    int bid = blockIdx.x;
    int i = bid * SCAN_BLK + tid;
    int v = (i < Nn) ? g_deg[i] : 0;
    if (i < Nn) g_dinv[i] = rsqrtf((float)v + 1.0f);
    int x = v;
    #pragma unroll
    for (int o = 1; o < 32; o <<= 1) {
        int t = __shfl_up_sync(0xffffffffu, x, o);
        if (lane >= o) x += t;
    }
    if (lane == 31) warp_sums[wid] = x;
    __syncthreads();
    if (wid == 0) {
        int s = warp_sums[lane];
        #pragma unroll
        for (int o = 1; o < 32; o <<= 1) {
            int t = __shfl_up_sync(0xffffffffu, s, o);
            if (lane >= o) s += t;
        }
        warp_sums[lane] = s;
    }
    __syncthreads();
    int incl = x + (wid > 0 ? warp_sums[wid - 1] : 0);   // block-local inclusive
    int btot = warp_sums[31];                            // block total
    if (tid == 0) {
        int prev = 0;
        if (bid > 0) {
            while (g_cflag[bid - 1] == 0) { }            // spin: predecessor co-resident
            __threadfence();
            prev = g_chain[bid - 1];
        }
        s_prefix = prev;
        g_chain[bid] = prev + btot;
        __threadfence();
        g_cflag[bid] = 1;
    }
    __syncthreads();
    if (i < Nn) {
        int ex = s_prefix + incl - v;                    // global exclusive prefix
        g_ptr[i] = ex;
        g_fill[i] = ex;                                  // running cursor for k_fill
    }
    if (bid == SCAN_NB - 1 && tid == SCAN_BLK - 1) g_ptr[Nn] = Ee;
}

__global__ void k_fill(const void* __restrict__ ei) {
    int e = blockIdx.x * blockDim.x + threadIdx.x;
    if (e < Ee) {
        const int is64 = g_is64;
        int d = edge_at(ei, 1, e, is64);
        int s = edge_at(ei, 0, e, is64);
        if (d >= 0 && d < Nn && s >= 0 && s < Nn) {
            int pos = atomicAdd(&g_fill[d], 1);          // cursor starts at ptr[d]
            if (pos >= 0 && pos < Ee) g_src[pos] = s;
        }
    }
}

// ---- dense GEMM (f32x2 math, fp16 output): Yh = half((X @ W) * dscale[row]) ----
// block = 256 threads, tile = 64 rows x OUTC cols, K-panels of 32
template <int OUTC>
__global__ void k_gemm(const float* __restrict__ X, const float* __restrict__ W,
                       const float* __restrict__ dscale,
                       __half* __restrict__ Yh, int nrows) {
    __shared__ float xs[64][33];          // padded to kill bank conflicts
    __shared__ __align__(16) float ws[32 * OUTC];
    constexpr int NH = OUTC / 64;          // 2 for 128, 1 for 64

    int tid  = threadIdx.x;
    int tx   = tid & 15;                   // col group
    int ty   = tid >> 4;                   // row group
    int row0 = blockIdx.x * 64;

    u64 acc2[4][NH * 2];                   // each u64 = 2 packed fp32 accumulators
    #pragma unroll
    for (int i = 0; i < 4; i++)
        #pragma unroll
        for (int j = 0; j < NH * 2; j++) acc2[i][j] = 0ULL;

    int lr = tid >> 2;                     // 0..63 : row for x-tile load
    int lc = (tid & 3) * 8;                // 0,8,16,24 : k-offset for x-tile load

    for (int k0 = 0; k0 < 128; k0 += 32) {
        if (row0 + lr < nrows) {
            const float* xp = X + (long)(row0 + lr) * 128 + k0 + lc;
            float4 v0 = *(const float4*)(xp);
            float4 v1 = *(const float4*)(xp + 4);
            xs[lr][lc + 0] = v0.x; xs[lr][lc + 1] = v0.y; xs[lr][lc + 2] = v0.z; xs[lr][lc + 3] = v0.w;
            xs[lr][lc + 4] = v1.x; xs[lr][lc + 5] = v1.y; xs[lr][lc + 6] = v1.z; xs[lr][lc + 7] = v1.w;
        } else {
            #pragma unroll
            for (int j = 0; j < 8; j++) xs[lr][lc + j] = 0.0f;
        }
        {
            const float4* wp = (const float4*)(W + k0 * OUTC);
            float4* wsp = (float4*)ws;
            #pragma unroll
            for (int f = 0; f < (32 * OUTC / 4) / 256; f++)
                wsp[tid + f * 256] = wp[tid + f * 256];
        }
        __syncthreads();

        #pragma unroll
        for (int kk = 0; kk < 32; kk++) {
            float a0 = xs[ty * 4 + 0][kk];
            float a1 = xs[ty * 4 + 1][kk];
            float a2 = xs[ty * 4 + 2][kk];
            float a3 = xs[ty * 4 + 3][kk];
            u64 a0p = pack2(a0, a0);
            u64 a1p = pack2(a1, a1);
            u64 a2p = pack2(a2, a2);
            u64 a3p = pack2(a3, a3);
            #pragma unroll
            for (int h2 = 0; h2 < NH; h2++) {
                const u64* wp2 = (const u64*)&ws[kk * OUTC + h2 * 64 + tx * 4];
                u64 w01 = wp2[0];
                u64 w23 = wp2[1];
                acc2[0][h2*2+0] = ffma2(a0p, w01, acc2[0][h2*2+0]);
                acc2[0][h2*2+1] = ffma2(a0p, w23, acc2[0][h2*2+1]);
                acc2[1][h2*2+0] = ffma2(a1p, w01, acc2[1][h2*2+0]);
                acc2[1][h2*2+1] = ffma2(a1p, w23, acc2[1][h2*2+1]);
                acc2[2][h2*2+0] = ffma2(a2p, w01, acc2[2][h2*2+0]);
                acc2[2][h2*2+1] = ffma2(a2p, w23, acc2[2][h2*2+1]);
                acc2[3][h2*2+0] = ffma2(a3p, w01, acc2[3][h2*2+0]);
                acc2[3][h2*2+1] = ffma2(a3p, w23, acc2[3][h2*2+1]);
            }
        }
        __syncthreads();
    }

    #pragma unroll
    for (int i = 0; i < 4; i++) {
        int row = row0 + ty * 4 + i;
        if (row < nrows) {
            float sc = dscale[row];
            #pragma unroll
            for (int h2 = 0; h2 < NH; h2++) {
                float4 v;
                unpack2(acc2[i][h2*2+0], v.x, v.y);
                unpack2(acc2[i][h2*2+1], v.z, v.w);
                v.x *= sc; v.y *= sc; v.z *= sc; v.w *= sc;
                __half2 p0 = __floats2half2_rn(v.x, v.y);
                __half2 p1 = __floats2half2_rn(v.z, v.w);
                uint2 pk = make_uint2(*(unsigned*)&p0, *(unsigned*)&p1);
                *(uint2*)&Yh[(long)row * OUTC + h2 * 64 + tx * 4] = pk;
            }
        }
    }
}

// ---- aggregation layer 1: warp per dst node, fp16 rows (256 B/row), fp32 accum ----
__global__ void k_agg1(const float* __restrict__ b1) {
    int warp = (blockIdx.x * blockDim.x + threadIdx.x) >> 5;
    int lane = threadIdx.x & 31;
    if (warp >= Nn) return;
    int node = warp;
    int beg = g_ptr[node], end = g_ptr[node + 1];
    float dd = g_dinv[node];
    const uint2* __restrict__ H1 = (const uint2*)g_h1;   // row = 32 uint2 (128 half)

    float4 acc = make_float4(0.f, 0.f, 0.f, 0.f);
    for (int e0 = beg; e0 < end; e0 += 32) {
        int n = end - e0; if (n > 32) n = 32;
        int myidx = (lane < n) ? g_src[e0 + lane] : 0;
        int j = 0;
        for (; j + 4 <= n; j += 4) {
            int s0 = __shfl_sync(0xffffffffu, myidx, j + 0);
            int s1 = __shfl_sync(0xffffffffu, myidx, j + 1);
            int s2 = __shfl_sync(0xffffffffu, myidx, j + 2);
            int s3 = __shfl_sync(0xffffffffu, myidx, j + 3);
            uint2 r0 = H1[(long)s0 * 32 + lane];
            uint2 r1 = H1[(long)s1 * 32 + lane];
            uint2 r2 = H1[(long)s2 * 32 + lane];
            uint2 r3 = H1[(long)s3 * 32 + lane];
            float2 a0 = __half22float2(*(__half2*)&r0.x), b0 = __half22float2(*(__half2*)&r0.y);
            float2 a1 = __half22float2(*(__half2*)&r1.x), b1v = __half22float2(*(__half2*)&r1.y);
            float2 a2 = __half22float2(*(__half2*)&r2.x), b2 = __half22float2(*(__half2*)&r2.y);
            float2 a3 = __half22float2(*(__half2*)&r3.x), b3 = __half22float2(*(__half2*)&r3.y);
            acc.x += a0.x + a1.x + a2.x + a3.x;
            acc.y += a0.y + a1.y + a2.y + a3.y;
            acc.z += b0.x + b1v.x + b2.x + b3.x;
            acc.w += b0.y + b1v.y + b2.y + b3.y;
        }
        for (; j < n; j++) {
            int s = __shfl_sync(0xffffffffu, myidx, j);
            uint2 r = H1[(long)s * 32 + lane];
            float2 a = __half22float2(*(__half2*)&r.x), b = __half22float2(*(__half2*)&r.y);
            acc.x += a.x; acc.y += a.y; acc.z += b.x; acc.w += b.y;
        }
    }
    uint2 rs = H1[(long)node * 32 + lane];               // self term (pre-scaled)
    float2 sa = __half22float2(*(__half2*)&rs.x), sb = __half22float2(*(__half2*)&rs.y);
    float4 b  = ((const float4*)b1)[lane];
    float4 r;
    r.x = fmaxf((acc.x + sa.x) * dd + b.x, 0.f);
    r.y = fmaxf((acc.y + sa.y) * dd + b.y, 0.f);
    r.z = fmaxf((acc.z + sb.x) * dd + b.z, 0.f);
    r.w = fmaxf((acc.w + sb.y) * dd + b.w, 0.f);
    ((float4*)g_h)[(long)node * 32 + lane] = r;
}

// ---- aggregation layer 2 + fused epilogue, fp16 rows (128 B/row) ----
__global__ void k_agg2(const float* __restrict__ bmu, const float* __restrict__ eps,
                       float* __restrict__ out) {
    int warp = (blockIdx.x * blockDim.x + threadIdx.x) >> 5;
    int lane = threadIdx.x & 31;
    if (warp >= Nn) return;
    int node = warp;
    int beg = g_ptr[node], end = g_ptr[node + 1];
    float dd = g_dinv[node];
    const __half2* __restrict__ M = (const __half2*)g_m2;  // row = 32 half2 (64 half)

    float2 acc = make_float2(0.f, 0.f);
    for (int e0 = beg; e0 < end; e0 += 32) {
        int n = end - e0; if (n > 32) n = 32;
        int myidx = (lane < n) ? g_src[e0 + lane] : 0;
        int j = 0;
        for (; j + 4 <= n; j += 4) {
            int s0 = __shfl_sync(0xffffffffu, myidx, j + 0);
            int s1 = __shfl_sync(0xffffffffu, myidx, j + 1);
            int s2 = __shfl_sync(0xffffffffu, myidx, j + 2);
            int s3 = __shfl_sync(0xffffffffu, myidx, j + 3);
            float2 v0 = __half22float2(M[(long)s0 * 32 + lane]);
            float2 v1 = __half22float2(M[(long)s1 * 32 + lane]);
            float2 v2 = __half22float2(M[(long)s2 * 32 + lane]);
            float2 v3 = __half22float2(M[(long)s3 * 32 + lane]);
            acc.x += v0.x + v1.x + v2.x + v3.x;
            acc.y += v0.y + v1.y + v2.y + v3.y;
        }
        for (; j < n; j++) {
            int s = __shfl_sync(0xffffffffu, myidx, j);
            float2 v = __half22float2(M[(long)s * 32 + lane]);
            acc.x += v.x; acc.y += v.y;
        }
    }
    float2 sf = __half22float2(M[(long)node * 32 + lane]);
    float2 b  = ((const float2*)bmu)[lane];
    float2 mu;
    mu.x = (acc.x + sf.x) * dd + b.x;
    mu.y = (acc.y + sf.y) * dd + b.y;

    float2 ep = ((const float2*)eps)[(long)node * 32 + lane];
    float2 z;
    z.x = mu.x + ep.x * __expf(mu.x);
    z.y = mu.y + ep.y * __expf(mu.y);

    long idx = (long)node * 32 + lane;
    ((float2*)out)[idx] = mu;                                   // mu
    ((float2*)(out + (long)Nn * OUTF))[idx] = mu;               // logstd == mu
    ((float2*)(out + 2L * Nn * OUTF))[idx] = z;                 // zeta
}

extern "C" void kernel_launch(void* const* d_in, const int* in_sizes, int n_in,
                              void* d_out, int out_size) {
    const float* x   = (const float*)d_in[0];
    const void*  ei  = d_in[1];                 // int64 or int32, detected on device
    const float* W1  = (const float*)d_in[2];
    const float* b1  = (const float*)d_in[3];
    const float* Wmu = (const float*)d_in[4];
    const float* bmu = (const float*)d_in[5];
    // d_in[6]=Wls, d_in[7]=bls are dead (reference reuses Wmu/bmu for logstd)
    const float* eps = (const float*)d_in[8];
    float* out = (float*)d_out;

    __half *h1p, *m2p;
    float *hp, *dvp;
    cudaGetSymbolAddress((void**)&h1p, g_h1);
    cudaGetSymbolAddress((void**)&hp,  g_h);
    cudaGetSymbolAddress((void**)&m2p, g_m2);
    cudaGetSymbolAddress((void**)&dvp, g_dinv);

    const int TB = 256;
    k_zero<<<(Nn + TB - 1) / TB, TB>>>(ei);     // zero + flag reset + dtype detection
    k_deg <<<(Ee + TB - 1) / TB, TB>>>(ei);
    k_scan<<<SCAN_NB, SCAN_BLK>>>();            // single-pass chained scan
    k_fill<<<(Ee + TB - 1) / TB, TB>>>(ei);

    k_gemm<HH><<<(Nn + 63) / 64, 256>>>(x, W1, dvp, h1p, Nn);
    k_agg1<<<(Nn * 32 + TB - 1) / TB, TB>>>(b1);
    k_gemm<OUTF><<<(Nn + 63) / 64, 256>>>(hp, Wmu, dvp, m2p, Nn);
    k_agg2<<<(Nn * 32 + TB - 1) / TB, TB>>>(bmu, eps, out);
}

// round 14
// speedup vs baseline: 1.4069x; 1.4069x over previous
#include <cuda_runtime.h>
#include <cuda_fp16.h>

#define Nn 50000
#define Ee 800000
#define INF 128
#define HH  128
#define OUTF 64
#define SCAN_BLK 1024
#define SCAN_NB ((Nn + SCAN_BLK - 1) / SCAN_BLK)   // 49

typedef unsigned long long u64;

// ---- packed f32x2 helpers ----
__device__ __forceinline__ u64 pack2(float lo, float hi) {
    u64 r; asm("mov.b64 %0, {%1, %2};" : "=l"(r) : "f"(lo), "f"(hi)); return r;
}
__device__ __forceinline__ void unpack2(u64 v, float& lo, float& hi) {
    asm("mov.b64 {%0, %1}, %2;" : "=f"(lo), "=f"(hi) : "l"(v));
}
__device__ __forceinline__ u64 ffma2(u64 a, u64 b, u64 c) {
    u64 d; asm("fma.rn.f32x2 %0, %1, %2, %3;" : "=l"(d) : "l"(a), "l"(b), "l"(c)); return d;
}

// ---- device scratch (static globals; no allocation) ----
__device__ __align__(16) __half g_h1[Nn * HH];   // (x @ W1) * dinv[row], fp16 for gather
__device__ __align__(16) float  g_h [Nn * HH];   // relu(conv1) output, fp32 (GEMM2 input)
__device__ __align__(16) __half g_m2[Nn * OUTF]; // (h @ Wmu) * dinv[row], fp16 for gather
__device__ int   g_deg [Nn];
__device__ int   g_ptr [Nn + 1];
__device__ int   g_fill[Nn];       // running cursor, initialized to ptr by scanC
__device__ int   g_src [Ee];       // CSR-by-dst neighbor lists
__device__ float g_dinv[Nn];
__device__ int   g_is64;           // 1 if edge_index is int64, 0 if int32
__device__ int   g_bsum[SCAN_NB];  // per-block degree sums
__device__ int   g_boff[SCAN_NB];  // exclusive prefix of block sums

__device__ __forceinline__ int edge_at(const void* ei, int which, int e, int is64) {
    // which: 0 = src row, 1 = dst row, layout [2, E]
    if (is64) return (int)((const long long*)ei)[(long)which * Ee + e];
    return ((const int*)ei)[(long)which * Ee + e];
}

// ---------------- zero + fused dtype detection ----------------
__global__ void k_zero(const void* ei) {
    int i = blockIdx.x * blockDim.x + threadIdx.x;
    if (i < Nn) g_deg[i] = 0;
    if (blockIdx.x == 0 && threadIdx.x < 32) {
        int lane = threadIdx.x;
        const long long* p = (const long long*)ei;
        long long v1 = p[lane];            // src row head
        long long v2 = p[Ee + lane];       // dst row head
        bool ok = (v1 >= 0 && v1 < Nn) && (v2 >= 0 && v2 < Nn);
        unsigned all = __all_sync(0xffffffffu, ok);
        if (lane == 0) g_is64 = all ? 1 : 0;
    }
}

__global__ void k_deg(const void* __restrict__ ei) {
    int e = blockIdx.x * blockDim.x + threadIdx.x;
    if (e < Ee) {
        const int is64 = g_is64;
        int d = edge_at(ei, 1, e, is64);
        if (d >= 0 && d < Nn) atomicAdd(&g_deg[d], 1);
    }
}

// ---- 3-phase multi-block scan (dinv fused into phase A, fill-init into phase C) ----
__global__ void k_scanA() {
    __shared__ int warp_sums[32];
    int tid = threadIdx.x, lane = tid & 31, wid = tid >> 5;
    int i = blockIdx.x * SCAN_BLK + tid;
    int v = (i < Nn) ? g_deg[i] : 0;
    if (i < Nn) g_dinv[i] = rsqrtf((float)v + 1.0f);   // fused dinv (only dep of gemm1)
    int x = v;
    #pragma unroll
    for (int o = 1; o < 32; o <<= 1) {
        int t = __shfl_up_sync(0xffffffffu, x, o);
        if (lane >= o) x += t;
    }
    if (lane == 31) warp_sums[wid] = x;
    __syncthreads();
    if (wid == 0) {
        int s = warp_sums[lane];
        #pragma unroll
        for (int o = 1; o < 32; o <<= 1) {
            int t = __shfl_up_sync(0xffffffffu, s, o);
            if (lane >= o) s += t;
        }
        warp_sums[lane] = s;
    }
    __syncthreads();
    int incl = x + (wid > 0 ? warp_sums[wid - 1] : 0);
    if (i < Nn) g_ptr[i] = incl - v;                 // block-local exclusive prefix
    if (tid == SCAN_BLK - 1) g_bsum[blockIdx.x] = incl;
}

__global__ void k_scanB() {
    int lane = threadIdx.x;
    int carry = 0;
    for (int base = 0; base < SCAN_NB; base += 32) {
        int idx = base + lane;
        int v = (idx < SCAN_NB) ? g_bsum[idx] : 0;
        int x = v;
        #pragma unroll
        for (int o = 1; o < 32; o <<= 1) {
            int t = __shfl_up_sync(0xffffffffu, x, o);
            if (lane >= o) x += t;
        }
        if (idx < SCAN_NB) g_boff[idx] = carry + x - v;
        carry += __shfl_sync(0xffffffffu, x, 31);
    }
    if (lane == 0) g_ptr[Nn] = Ee;                   // total degree == E (all dst valid)
}

__global__ void k_scanC() {
    int i = blockIdx.x * SCAN_BLK + threadIdx.x;
    if (i < Nn) {
        int p = g_ptr[i] + g_boff[blockIdx.x];
        g_ptr[i] = p;
        g_fill[i] = p;                               // running cursor for k_fill
    }
}

__global__ void k_fill(const void* __restrict__ ei) {
    int e = blockIdx.x * blockDim.x + threadIdx.x;
    if (e < Ee) {
        const int is64 = g_is64;
        int d = edge_at(ei, 1, e, is64);
        int s = edge_at(ei, 0, e, is64);
        if (d >= 0 && d < Nn && s >= 0 && s < Nn) {
            int pos = atomicAdd(&g_fill[d], 1);      // cursor starts at ptr[d]
            if (pos >= 0 && pos < Ee) g_src[pos] = s;
        }
    }
}

// ---- dense GEMM (f32x2 math, fp16 output): Yh = half((X @ W) * dscale[row]) ----
template <int OUTC>
__global__ void k_gemm(const float* __restrict__ X, const float* __restrict__ W,
                       const float* __restrict__ dscale,
                       __half* __restrict__ Yh, int nrows) {
    __shared__ float xs[64][33];
    __shared__ __align__(16) float ws[32 * OUTC];
    constexpr int NH = OUTC / 64;

    int tid  = threadIdx.x;
    int tx   = tid & 15;
    int ty   = tid >> 4;
    int row0 = blockIdx.x * 64;

    u64 acc2[4][NH * 2];
    #pragma unroll
    for (int i = 0; i < 4; i++)
        #pragma unroll
        for (int j = 0; j < NH * 2; j++) acc2[i][j] = 0ULL;

    int lr = tid >> 2;
    int lc = (tid & 3) * 8;

    for (int k0 = 0; k0 < 128; k0 += 32) {
        if (row0 + lr < nrows) {
            const float* xp = X + (long)(row0 + lr) * 128 + k0 + lc;
            float4 v0 = *(const float4*)(xp);
            float4 v1 = *(const float4*)(xp + 4);
            xs[lr][lc + 0] = v0.x; xs[lr][lc + 1] = v0.y; xs[lr][lc + 2] = v0.z; xs[lr][lc + 3] = v0.w;
            xs[lr][lc + 4] = v1.x; xs[lr][lc + 5] = v1.y; xs[lr][lc + 6] = v1.z; xs[lr][lc + 7] = v1.w;
        } else {
            #pragma unroll
            for (int j = 0; j < 8; j++) xs[lr][lc + j] = 0.0f;
        }
        {
            const float4* wp = (const float4*)(W + k0 * OUTC);
            float4* wsp = (float4*)ws;
            #pragma unroll
            for (int f = 0; f < (32 * OUTC / 4) / 256; f++)
                wsp[tid + f * 256] = wp[tid + f * 256];
        }
        __syncthreads();

        #pragma unroll
        for (int kk = 0; kk < 32; kk++) {
            float a0 = xs[ty * 4 + 0][kk];
            float a1 = xs[ty * 4 + 1][kk];
            float a2 = xs[ty * 4 + 2][kk];
            float a3 = xs[ty * 4 + 3][kk];
            u64 a0p = pack2(a0, a0);
            u64 a1p = pack2(a1, a1);
            u64 a2p = pack2(a2, a2);
            u64 a3p = pack2(a3, a3);
            #pragma unroll
            for (int h2 = 0; h2 < NH; h2++) {
                const u64* wp2 = (const u64*)&ws[kk * OUTC + h2 * 64 + tx * 4];
                u64 w01 = wp2[0];
                u64 w23 = wp2[1];
                acc2[0][h2*2+0] = ffma2(a0p, w01, acc2[0][h2*2+0]);
                acc2[0][h2*2+1] = ffma2(a0p, w23, acc2[0][h2*2+1]);
                acc2[1][h2*2+0] = ffma2(a1p, w01, acc2[1][h2*2+0]);
                acc2[1][h2*2+1] = ffma2(a1p, w23, acc2[1][h2*2+1]);
                acc2[2][h2*2+0] = ffma2(a2p, w01, acc2[2][h2*2+0]);
                acc2[2][h2*2+1] = ffma2(a2p, w23, acc2[2][h2*2+1]);
                acc2[3][h2*2+0] = ffma2(a3p, w01, acc2[3][h2*2+0]);
                acc2[3][h2*2+1] = ffma2(a3p, w23, acc2[3][h2*2+1]);
            }
        }
        __syncthreads();
    }

    #pragma unroll
    for (int i = 0; i < 4; i++) {
        int row = row0 + ty * 4 + i;
        if (row < nrows) {
            float sc = dscale[row];
            #pragma unroll
            for (int h2 = 0; h2 < NH; h2++) {
                float4 v;
                unpack2(acc2[i][h2*2+0], v.x, v.y);
                unpack2(acc2[i][h2*2+1], v.z, v.w);
                v.x *= sc; v.y *= sc; v.z *= sc; v.w *= sc;
                __half2 p0 = __floats2half2_rn(v.x, v.y);
                __half2 p1 = __floats2half2_rn(v.z, v.w);
                uint2 pk = make_uint2(*(unsigned*)&p0, *(unsigned*)&p1);
                *(uint2*)&Yh[(long)row * OUTC + h2 * 64 + tx * 4] = pk;
            }
        }
    }
}

// ---- aggregation layer 1: warp per dst node, fp16 rows (256 B/row), fp32 accum ----
__global__ void k_agg1(const float* __restrict__ b1) {
    int warp = (blockIdx.x * blockDim.x + threadIdx.x) >> 5;
    int lane = threadIdx.x & 31;
    if (warp >= Nn) return;
    int node = warp;
    int beg = g_ptr[node], end = g_ptr[node + 1];
    float dd = g_dinv[node];
    const uint2* __restrict__ H1 = (const uint2*)g_h1;   // row = 32 uint2 (128 half)

    float4 acc = make_float4(0.f, 0.f, 0.f, 0.f);
    for (int e0 = beg; e0 < end; e0 += 32) {
        int n = end - e0; if (n > 32) n = 32;
        int myidx = (lane < n) ? g_src[e0 + lane] : 0;
        int j = 0;
        for (; j + 4 <= n; j += 4) {
            int s0 = __shfl_sync(0xffffffffu, myidx, j + 0);
            int s1 = __shfl_sync(0xffffffffu, myidx, j + 1);
            int s2 = __shfl_sync(0xffffffffu, myidx, j + 2);
            int s3 = __shfl_sync(0xffffffffu, myidx, j + 3);
            uint2 r0 = H1[(long)s0 * 32 + lane];
            uint2 r1 = H1[(long)s1 * 32 + lane];
            uint2 r2 = H1[(long)s2 * 32 + lane];
            uint2 r3 = H1[(long)s3 * 32 + lane];
            float2 a0 = __half22float2(*(__half2*)&r0.x), b0 = __half22float2(*(__half2*)&r0.y);
            float2 a1 = __half22float2(*(__half2*)&r1.x), b1v = __half22float2(*(__half2*)&r1.y);
            float2 a2 = __half22float2(*(__half2*)&r2.x), b2 = __half22float2(*(__half2*)&r2.y);
            float2 a3 = __half22float2(*(__half2*)&r3.x), b3 = __half22float2(*(__half2*)&r3.y);
            acc.x += a0.x + a1.x + a2.x + a3.x;
            acc.y += a0.y + a1.y + a2.y + a3.y;
            acc.z += b0.x + b1v.x + b2.x + b3.x;
            acc.w += b0.y + b1v.y + b2.y + b3.y;
        }
        for (; j < n; j++) {
            int s = __shfl_sync(0xffffffffu, myidx, j);
            uint2 r = H1[(long)s * 32 + lane];
            float2 a = __half22float2(*(__half2*)&r.x), b = __half22float2(*(__half2*)&r.y);
            acc.x += a.x; acc.y += a.y; acc.z += b.x; acc.w += b.y;
        }
    }
    uint2 rs = H1[(long)node * 32 + lane];               // self term (pre-scaled)
    float2 sa = __half22float2(*(__half2*)&rs.x), sb = __half22float2(*(__half2*)&rs.y);
    float4 b  = ((const float4*)b1)[lane];
    float4 r;
    r.x = fmaxf((acc.x + sa.x) * dd + b.x, 0.f);
    r.y = fmaxf((acc.y + sa.y) * dd + b.y, 0.f);
    r.z = fmaxf((acc.z + sb.x) * dd + b.z, 0.f);
    r.w = fmaxf((acc.w + sb.y) * dd + b.w, 0.f);
    ((float4*)g_h)[(long)node * 32 + lane] = r;
}

// ---- aggregation layer 2 + fused epilogue, fp16 rows (128 B/row) ----
__global__ void k_agg2(const float* __restrict__ bmu, const float* __restrict__ eps,
                       float* __restrict__ out) {
    int warp = (blockIdx.x * blockDim.x + threadIdx.x) >> 5;
    int lane = threadIdx.x & 31;
    if (warp >= Nn) return;
    int node = warp;
    int beg = g_ptr[node], end = g_ptr[node + 1];
    float dd = g_dinv[node];
    const __half2* __restrict__ M = (const __half2*)g_m2;  // row = 32 half2 (64 half)

    float2 acc = make_float2(0.f, 0.f);
    for (int e0 = beg; e0 < end; e0 += 32) {
        int n = end - e0; if (n > 32) n = 32;
        int myidx = (lane < n) ? g_src[e0 + lane] : 0;
        int j = 0;
        for (; j + 4 <= n; j += 4) {
            int s0 = __shfl_sync(0xffffffffu, myidx, j + 0);
            int s1 = __shfl_sync(0xffffffffu, myidx, j + 1);
            int s2 = __shfl_sync(0xffffffffu, myidx, j + 2);
            int s3 = __shfl_sync(0xffffffffu, myidx, j + 3);
            float2 v0 = __half22float2(M[(long)s0 * 32 + lane]);
            float2 v1 = __half22float2(M[(long)s1 * 32 + lane]);
            float2 v2 = __half22float2(M[(long)s2 * 32 + lane]);
            float2 v3 = __half22float2(M[(long)s3 * 32 + lane]);
            acc.x += v0.x + v1.x + v2.x + v3.x;
            acc.y += v0.y + v1.y + v2.y + v3.y;
        }
        for (; j < n; j++) {
            int s = __shfl_sync(0xffffffffu, myidx, j);
            float2 v = __half22float2(M[(long)s * 32 + lane]);
            acc.x += v.x; acc.y += v.y;
        }
    }
    float2 sf = __half22float2(M[(long)node * 32 + lane]);
    float2 b  = ((const float2*)bmu)[lane];
    float2 mu;
    mu.x = (acc.x + sf.x) * dd + b.x;
    mu.y = (acc.y + sf.y) * dd + b.y;

    float2 ep = ((const float2*)eps)[(long)node * 32 + lane];
    float2 z;
    z.x = mu.x + ep.x * __expf(mu.x);
    z.y = mu.y + ep.y * __expf(mu.y);

    long idx = (long)node * 32 + lane;
    ((float2*)out)[idx] = mu;                                   // mu
    ((float2*)(out + (long)Nn * OUTF))[idx] = mu;               // logstd == mu
    ((float2*)(out + 2L * Nn * OUTF))[idx] = z;                 // zeta
}

extern "C" void kernel_launch(void* const* d_in, const int* in_sizes, int n_in,
                              void* d_out, int out_size) {
    const float* x   = (const float*)d_in[0];
    const void*  ei  = d_in[1];                 // int64 or int32, detected on device
    const float* W1  = (const float*)d_in[2];
    const float* b1  = (const float*)d_in[3];
    const float* Wmu = (const float*)d_in[4];
    const float* bmu = (const float*)d_in[5];
    // d_in[6]=Wls, d_in[7]=bls are dead (reference reuses Wmu/bmu for logstd)
    const float* eps = (const float*)d_in[8];
    float* out = (float*)d_out;

    __half *h1p, *m2p;
    float *hp, *dvp;
    cudaGetSymbolAddress((void**)&h1p, g_h1);
    cudaGetSymbolAddress((void**)&hp,  g_h);
    cudaGetSymbolAddress((void**)&m2p, g_m2);
    cudaGetSymbolAddress((void**)&dvp, g_dinv);

    const int TB = 256;
    k_zero<<<(Nn + TB - 1) / TB, TB>>>(ei);              // #1 zero + dtype detection
    k_deg <<<(Ee + TB - 1) / TB, TB>>>(ei);              // #2
    k_scanA<<<SCAN_NB, SCAN_BLK>>>();                    // #3 (produces dinv)
    k_gemm<HH><<<(Nn + 63) / 64, 256>>>(x, W1, dvp, h1p, Nn);  // #4 <- profiled slot
    k_scanB<<<1, 32>>>();                                // #5
    k_scanC<<<SCAN_NB, SCAN_BLK>>>();                    // #6 (ptr final + fill init)
    k_fill<<<(Ee + TB - 1) / TB, TB>>>(ei);              // #7
    k_agg1<<<(Nn * 32 + TB - 1) / TB, TB>>>(b1);         // #8
    k_gemm<OUTF><<<(Nn + 63) / 64, 256>>>(hp, Wmu, dvp, m2p, Nn);  // #9
    k_agg2<<<(Nn * 32 + TB - 1) / TB, TB>>>(bmu, eps, out);        // #10
}